// round 1
// baseline (speedup 1.0000x reference)
#include <cuda_runtime.h>
#include <math.h>

#define BB 512
#define HH 2048
#define EE 2048
#define TT 256
#define KC 16

// Scratch state (allocation-free rule: __device__ globals)
__device__ float g_h[2][BB * HH];   // ping-pong hidden state
__device__ float g_c[BB * HH];      // cell state (in-place safe: 1 reader/writer per elem)

__device__ __forceinline__ float sigm(float x) { return 1.0f / (1.0f + expf(-x)); }

__global__ void zero_c_kernel() {
    int i = blockIdx.x * blockDim.x + threadIdx.x;
    if (i < BB * HH) g_c[i] = 0.0f;
}

// h0 = embedding @ W_embed^T + b_embed   -> g_h[0]
__global__ __launch_bounds__(256, 2)
void h0_kernel(const float* __restrict__ emb, const float* __restrict__ W,
               const float* __restrict__ bias) {
    __shared__ float As[KC][64];
    __shared__ float Bs[KC][64];
    int tid = threadIdx.x;
    int m0 = blockIdx.y * 64, n0 = blockIdx.x * 64;
    int lrow = tid >> 2, lk4 = (tid & 3) * 4;
    int tx_m = tid >> 4, tx_n = tid & 15;

    float acc[4][4];
#pragma unroll
    for (int i = 0; i < 4; i++)
#pragma unroll
        for (int j = 0; j < 4; j++) acc[i][j] = 0.0f;

    for (int k0 = 0; k0 < EE; k0 += KC) {
        float4 av = *(const float4*)&emb[(m0 + lrow) * EE + k0 + lk4];
        float4 bv = *(const float4*)&W[(n0 + lrow) * EE + k0 + lk4];
        __syncthreads();
        As[lk4 + 0][lrow] = av.x; As[lk4 + 1][lrow] = av.y;
        As[lk4 + 2][lrow] = av.z; As[lk4 + 3][lrow] = av.w;
        Bs[lk4 + 0][lrow] = bv.x; Bs[lk4 + 1][lrow] = bv.y;
        Bs[lk4 + 2][lrow] = bv.z; Bs[lk4 + 3][lrow] = bv.w;
        __syncthreads();
#pragma unroll
        for (int kk = 0; kk < KC; kk++) {
            float a[4], b[4];
            *(float4*)a = *(float4*)&As[kk][tx_m * 4];
            *(float4*)b = *(float4*)&Bs[kk][tx_n * 4];
#pragma unroll
            for (int mi = 0; mi < 4; mi++)
#pragma unroll
                for (int ni = 0; ni < 4; ni++) acc[mi][ni] += a[mi] * b[ni];
        }
    }
#pragma unroll
    for (int mi = 0; mi < 4; mi++) {
        int m = m0 + tx_m * 4 + mi;
#pragma unroll
        for (int ni = 0; ni < 4; ni++) {
            int n = n0 + tx_n * 4 + ni;
            g_h[0][m * HH + n] = acc[mi][ni] + bias[n];
        }
    }
}

// One LSTM step: gates = h_prev @ W_hh^T + x @ W_ih^T + b_ih + b_hh,
// then c/h update fused in epilogue. x = coords from step t-1 (read from d_out).
__global__ __launch_bounds__(256, 2)
void lstm_step_kernel(const float* __restrict__ W_hh, const float* __restrict__ b_hh,
                      const float* __restrict__ W_ih, const float* __restrict__ b_ih,
                      const float* __restrict__ out, int t) {
    __shared__ float As[KC][64];
    __shared__ float Bs[4][KC][64];

    const float* h_prev = g_h[t & 1];
    float* h_next = g_h[(t & 1) ^ 1];

    int tid = threadIdx.x;
    int m0 = blockIdx.y * 64, n0 = blockIdx.x * 64;
    int lrow = tid >> 2, lk4 = (tid & 3) * 4;
    int tx_m = tid >> 4, tx_n = tid & 15;

    float acc[4][4][4];  // [gate][mi][ni]
#pragma unroll
    for (int g = 0; g < 4; g++)
#pragma unroll
        for (int i = 0; i < 4; i++)
#pragma unroll
            for (int j = 0; j < 4; j++) acc[g][i][j] = 0.0f;

    for (int k0 = 0; k0 < HH; k0 += KC) {
        float4 av = *(const float4*)&h_prev[(m0 + lrow) * HH + k0 + lk4];
        float4 bv[4];
#pragma unroll
        for (int g = 0; g < 4; g++)
            bv[g] = *(const float4*)&W_hh[(g * HH + n0 + lrow) * HH + k0 + lk4];
        __syncthreads();
        As[lk4 + 0][lrow] = av.x; As[lk4 + 1][lrow] = av.y;
        As[lk4 + 2][lrow] = av.z; As[lk4 + 3][lrow] = av.w;
#pragma unroll
        for (int g = 0; g < 4; g++) {
            Bs[g][lk4 + 0][lrow] = bv[g].x; Bs[g][lk4 + 1][lrow] = bv[g].y;
            Bs[g][lk4 + 2][lrow] = bv[g].z; Bs[g][lk4 + 3][lrow] = bv[g].w;
        }
        __syncthreads();
#pragma unroll
        for (int kk = 0; kk < KC; kk++) {
            float a[4], b[4][4];
            *(float4*)a = *(float4*)&As[kk][tx_m * 4];
#pragma unroll
            for (int g = 0; g < 4; g++)
                *(float4*)b[g] = *(float4*)&Bs[g][kk][tx_n * 4];
#pragma unroll
            for (int g = 0; g < 4; g++)
#pragma unroll
                for (int mi = 0; mi < 4; mi++)
#pragma unroll
                    for (int ni = 0; ni < 4; ni++)
                        acc[g][mi][ni] += a[mi] * b[g][ni];
        }
    }

    // Fused LSTM epilogue
#pragma unroll
    for (int mi = 0; mi < 4; mi++) {
        int m = m0 + tx_m * 4 + mi;
        float x0 = 0.0f, x1 = 0.0f;
        if (t > 0) {
            x0 = out[(m * TT + t - 1) * 2 + 0];
            x1 = out[(m * TT + t - 1) * 2 + 1];
        }
#pragma unroll
        for (int ni = 0; ni < 4; ni++) {
            int hc = n0 + tx_n * 4 + ni;
            float pre[4];
#pragma unroll
            for (int g = 0; g < 4; g++) {
                int j = g * HH + hc;
                pre[g] = acc[g][mi][ni] + b_ih[j] + b_hh[j]
                       + x0 * W_ih[2 * j + 0] + x1 * W_ih[2 * j + 1];
            }
            float ig = sigm(pre[0]);
            float fg = sigm(pre[1]);
            float gg = tanhf(pre[2]);
            float og = sigm(pre[3]);
            float cp = g_c[m * HH + hc];
            float cn = fg * cp + ig * gg;
            g_c[m * HH + hc] = cn;
            h_next[m * HH + hc] = og * tanhf(cn);
        }
    }
}

// coord = h @ W_out^T + b_out ; stop = sigmoid(h @ W_stop^T + b_stop)
// out layout: coords (B,T,2) at [0, B*T*2), stops (B,T,1) at [B*T*2, B*T*3)
__global__ void head_kernel(const float* __restrict__ W_out, const float* __restrict__ b_out,
                            const float* __restrict__ W_stop, const float* __restrict__ b_stop,
                            float* __restrict__ out, int t) {
    int b = blockIdx.x;
    const float* h = g_h[(t & 1) ^ 1] + b * HH;
    int tid = threadIdx.x;  // 128 threads

    float s0 = 0.0f, s1 = 0.0f, ss = 0.0f;
    for (int i = tid; i < HH; i += 128) {
        float hv = h[i];
        s0 += hv * W_out[i];
        s1 += hv * W_out[HH + i];
        ss += hv * W_stop[i];
    }
#pragma unroll
    for (int o = 16; o > 0; o >>= 1) {
        s0 += __shfl_down_sync(0xFFFFFFFFu, s0, o);
        s1 += __shfl_down_sync(0xFFFFFFFFu, s1, o);
        ss += __shfl_down_sync(0xFFFFFFFFu, ss, o);
    }
    __shared__ float r0[4], r1[4], rs[4];
    int w = tid >> 5;
    if ((tid & 31) == 0) { r0[w] = s0; r1[w] = s1; rs[w] = ss; }
    __syncthreads();
    if (tid == 0) {
        float t0 = r0[0] + r0[1] + r0[2] + r0[3];
        float t1 = r1[0] + r1[1] + r1[2] + r1[3];
        float ts = rs[0] + rs[1] + rs[2] + rs[3];
        out[(b * TT + t) * 2 + 0] = t0 + b_out[0];
        out[(b * TT + t) * 2 + 1] = t1 + b_out[1];
        out[BB * TT * 2 + b * TT + t] = sigm(ts + b_stop[0]);
    }
}

extern "C" void kernel_launch(void* const* d_in, const int* in_sizes, int n_in,
                              void* d_out, int out_size) {
    const float* emb     = (const float*)d_in[0];
    // d_in[1] = max_seq_length (256, baked in as TT)
    const float* W_embed = (const float*)d_in[2];
    const float* b_embed = (const float*)d_in[3];
    const float* W_ih    = (const float*)d_in[4];
    const float* b_ih    = (const float*)d_in[5];
    const float* W_hh    = (const float*)d_in[6];
    const float* b_hh    = (const float*)d_in[7];
    const float* W_out   = (const float*)d_in[8];
    const float* b_out   = (const float*)d_in[9];
    const float* W_stop  = (const float*)d_in[10];
    const float* b_stop  = (const float*)d_in[11];
    float* out = (float*)d_out;

    zero_c_kernel<<<(BB * HH + 255) / 256, 256>>>();
    h0_kernel<<<dim3(HH / 64, BB / 64), 256>>>(emb, W_embed, b_embed);

    for (int t = 0; t < TT; t++) {
        lstm_step_kernel<<<dim3(HH / 64, BB / 64), 256>>>(W_hh, b_hh, W_ih, b_ih, out, t);
        head_kernel<<<BB, 128>>>(W_out, b_out, W_stop, b_stop, out, t);
    }
}

// round 3
// speedup vs baseline: 2.4542x; 2.4542x over previous
#include <cuda_runtime.h>
#include <cuda_bf16.h>
#include <math.h>
#include <cstdint>

#define BB 512
#define HH 2048
#define EE 2048
#define TT 256
#define NG 8192    // 4*H, permuted: n' = hc*4 + gate (i,f,g,o)

// ------------------------------------------------------------------ state
__device__ __align__(128) __nv_bfloat16 g_h_hi[2][BB * HH];
__device__ __align__(128) __nv_bfloat16 g_h_lo[2][BB * HH];
__device__ __align__(128) float         g_c[BB * HH];
__device__ __align__(128) __nv_bfloat16 g_w_hi[NG * HH];
__device__ __align__(128) __nv_bfloat16 g_w_lo[NG * HH];
__device__ __align__(128) float         g_bsum[NG];
__device__ __align__(128) float         g_wih0[NG];
__device__ __align__(128) float         g_wih1[NG];

// ------------------------------------------------------------------ helpers
#define CP16(dst, src)  asm volatile("cp.async.cg.shared.global [%0], [%1], 16;" :: "r"(dst), "l"(src))
#define CP_COMMIT()     asm volatile("cp.async.commit_group;" ::: "memory")
#define CP_WAIT1()      asm volatile("cp.async.wait_group 1;" ::: "memory")

__device__ __forceinline__ uint32_t smem_u32(const void* p) {
    uint32_t a;
    asm("{ .reg .u64 t; cvta.to.shared.u64 t, %1; cvt.u32.u64 %0, t; }" : "=r"(a) : "l"(p));
    return a;
}

__device__ __forceinline__ void mma16816(float* d, const uint32_t* a, const uint32_t* b) {
    asm volatile(
        "mma.sync.aligned.m16n8k16.row.col.f32.bf16.bf16.f32 "
        "{%0,%1,%2,%3}, {%4,%5,%6,%7}, {%8,%9}, {%0,%1,%2,%3};"
        : "+f"(d[0]), "+f"(d[1]), "+f"(d[2]), "+f"(d[3])
        : "r"(a[0]), "r"(a[1]), "r"(a[2]), "r"(a[3]), "r"(b[0]), "r"(b[1]));
}

__device__ __forceinline__ float fsigm(float x) { return 1.0f / (1.0f + __expf(-x)); }
__device__ __forceinline__ float ftanh(float x) {
    if (x > 8.0f) return 1.0f;
    if (x < -8.0f) return -1.0f;
    float e = __expf(2.0f * x);
    return (e - 1.0f) / (e + 1.0f);
}

// ------------------------------------------------------------------ prep
__global__ void prep_w_kernel(const float* __restrict__ W_hh) {
    int np = blockIdx.x;                 // 0..NG-1
    int g = np & 3, hc = np >> 2;
    const float* src = W_hh + (size_t)(g * HH + hc) * HH;
    __nv_bfloat16* dh = g_w_hi + (size_t)np * HH;
    __nv_bfloat16* dl = g_w_lo + (size_t)np * HH;
#pragma unroll
    for (int j = 0; j < HH / 256; j++) {
        int k = threadIdx.x + j * 256;
        float w = src[k];
        __nv_bfloat16 hi = __float2bfloat16_rn(w);
        dh[k] = hi;
        dl[k] = __float2bfloat16_rn(w - __bfloat162float(hi));
    }
}

__global__ void prep_misc_kernel(const float* __restrict__ b_ih, const float* __restrict__ b_hh,
                                 const float* __restrict__ W_ih) {
    int np = blockIdx.x * 256 + threadIdx.x;
    int g = np & 3, hc = np >> 2;
    int j = g * HH + hc;
    g_bsum[np] = b_ih[j] + b_hh[j];
    g_wih0[np] = W_ih[2 * j + 0];
    g_wih1[np] = W_ih[2 * j + 1];
}

// ------------------------------------------------------------------ h0 (fp32 SIMT, one-time)
#define KC 16
__global__ __launch_bounds__(256, 2)
void h0_kernel(const float* __restrict__ emb, const float* __restrict__ W,
               const float* __restrict__ bias) {
    __shared__ float As[KC][64];
    __shared__ float Bs[KC][64];
    int tid = threadIdx.x;
    int m0 = blockIdx.y * 64, n0 = blockIdx.x * 64;
    int lrow = tid >> 2, lk4 = (tid & 3) * 4;
    int tx_m = tid >> 4, tx_n = tid & 15;

    float acc[4][4];
#pragma unroll
    for (int i = 0; i < 4; i++)
#pragma unroll
        for (int j = 0; j < 4; j++) acc[i][j] = 0.0f;

    for (int k0 = 0; k0 < EE; k0 += KC) {
        float4 av = *(const float4*)&emb[(m0 + lrow) * EE + k0 + lk4];
        float4 bv = *(const float4*)&W[(n0 + lrow) * EE + k0 + lk4];
        __syncthreads();
        As[lk4 + 0][lrow] = av.x; As[lk4 + 1][lrow] = av.y;
        As[lk4 + 2][lrow] = av.z; As[lk4 + 3][lrow] = av.w;
        Bs[lk4 + 0][lrow] = bv.x; Bs[lk4 + 1][lrow] = bv.y;
        Bs[lk4 + 2][lrow] = bv.z; Bs[lk4 + 3][lrow] = bv.w;
        __syncthreads();
#pragma unroll
        for (int kk = 0; kk < KC; kk++) {
            float a[4], b[4];
            *(float4*)a = *(float4*)&As[kk][tx_m * 4];
            *(float4*)b = *(float4*)&Bs[kk][tx_n * 4];
#pragma unroll
            for (int mi = 0; mi < 4; mi++)
#pragma unroll
                for (int ni = 0; ni < 4; ni++) acc[mi][ni] += a[mi] * b[ni];
        }
    }
#pragma unroll
    for (int mi = 0; mi < 4; mi++) {
        int m = m0 + tx_m * 4 + mi;
#pragma unroll
        for (int ni = 0; ni < 4; ni++) {
            int n = n0 + tx_n * 4 + ni;
            float h = acc[mi][ni] + bias[n];
            __nv_bfloat16 hi = __float2bfloat16_rn(h);
            g_h_hi[0][m * HH + n] = hi;
            g_h_lo[0][m * HH + n] = __float2bfloat16_rn(h - __bfloat162float(hi));
        }
    }
}

// ------------------------------------------------------------------ main LSTM step (mma.sync bf16 3-pass)
// CTA tile: 128 M x 256 N. Grid (32, 4). 512 threads = 16 warps of 32x64.
#define BKC 32           // K per chunk
#define ROWB 80          // padded row bytes (32 bf16 = 64B data + 16B pad)
#define NCHUNK 64        // 2048 / 32
#define A_HI_OFF 0
#define A_LO_OFF 10240   // 128*80
#define B_HI_OFF 20480
#define B_LO_OFF 40960   // + 256*80
#define STAGE_BYTES 61440
#define XS_OFF 0
#define STAGE0 1024
#define SMEM_TOTAL (STAGE0 + 3 * STAGE_BYTES)

__device__ __forceinline__ void load_chunk(char* smem, int stage_idx, int k0, int m0, int n0,
                                           const __nv_bfloat16* hh, const __nv_bfloat16* hl,
                                           int tid) {
    uint32_t st = smem_u32(smem + STAGE0 + stage_idx * STAGE_BYTES);
    {   // A: 128 rows x 4 chunks of 16B, one per thread
        int row = tid >> 2, c16 = tid & 3;
        uint32_t d = st + row * ROWB + c16 * 16;
        size_t goff = (size_t)(m0 + row) * HH + k0 + c16 * 8;
        CP16(d + A_HI_OFF, hh + goff);
        CP16(d + A_LO_OFF, hl + goff);
    }
#pragma unroll
    for (int p = 0; p < 2; p++) {   // B: 256 rows x 4 chunks, two per thread
        int u = tid + p * 512;
        int row = u >> 2, c16 = u & 3;
        uint32_t d = st + row * ROWB + c16 * 16;
        size_t goff = (size_t)(n0 + row) * HH + k0 + c16 * 8;
        CP16(d + B_HI_OFF, g_w_hi + goff);
        CP16(d + B_LO_OFF, g_w_lo + goff);
    }
}

__global__ __launch_bounds__(512, 1)
void lstm_step_mma(const float* __restrict__ out, int t) {
    extern __shared__ char smem[];
    float* x_s = (float*)(smem + XS_OFF);       // [128][2]
    int tid = threadIdx.x;
    int wid = tid >> 5, lane = tid & 31;
    int g = lane >> 2, tig = lane & 3;
    int wm = wid & 3, wn = wid >> 2;            // 4 x 4 warps
    int n0 = blockIdx.x * 256, m0 = blockIdx.y * 128;
    int src = t & 1, dst = src ^ 1;
    const __nv_bfloat16* hh = g_h_hi[src];
    const __nv_bfloat16* hl = g_h_lo[src];

    // prev coords -> smem
    if (tid < 128) {
        float x0 = 0.0f, x1 = 0.0f;
        if (t > 0) {
            x0 = out[((m0 + tid) * TT + t - 1) * 2 + 0];
            x1 = out[((m0 + tid) * TT + t - 1) * 2 + 1];
        }
        x_s[tid * 2 + 0] = x0;
        x_s[tid * 2 + 1] = x1;
    }

    float acc[2][8][4];
#pragma unroll
    for (int mi = 0; mi < 2; mi++)
#pragma unroll
        for (int ni = 0; ni < 8; ni++)
#pragma unroll
            for (int j = 0; j < 4; j++) acc[mi][ni][j] = 0.0f;

    load_chunk(smem, 0, 0, m0, n0, hh, hl, tid);
    CP_COMMIT();
    load_chunk(smem, 1, BKC, m0, n0, hh, hl, tid);
    CP_COMMIT();

    for (int c = 0; c < NCHUNK; c++) {
        CP_WAIT1();
        __syncthreads();
        if (c + 2 < NCHUNK)
            load_chunk(smem, (c + 2) % 3, (c + 2) * BKC, m0, n0, hh, hl, tid);
        CP_COMMIT();

        char* stage = smem + STAGE0 + (c % 3) * STAGE_BYTES;
#pragma unroll
        for (int kk = 0; kk < 2; kk++) {
            int kb = kk * 32;   // bytes: k16 offset *2B
            uint32_t ah[2][4], al[2][4];
#pragma unroll
            for (int mi = 0; mi < 2; mi++) {
                const char* ap = stage + (wm * 32 + mi * 16 + g) * ROWB + kb + tig * 4;
                ah[mi][0] = *(const uint32_t*)(ap + A_HI_OFF);
                ah[mi][1] = *(const uint32_t*)(ap + A_HI_OFF + 8 * ROWB);
                ah[mi][2] = *(const uint32_t*)(ap + A_HI_OFF + 16);
                ah[mi][3] = *(const uint32_t*)(ap + A_HI_OFF + 8 * ROWB + 16);
                al[mi][0] = *(const uint32_t*)(ap + A_LO_OFF);
                al[mi][1] = *(const uint32_t*)(ap + A_LO_OFF + 8 * ROWB);
                al[mi][2] = *(const uint32_t*)(ap + A_LO_OFF + 16);
                al[mi][3] = *(const uint32_t*)(ap + A_LO_OFF + 8 * ROWB + 16);
            }
#pragma unroll
            for (int ni = 0; ni < 8; ni++) {
                const char* bp = stage + (wn * 64 + ni * 8 + g) * ROWB + kb + tig * 4;
                uint32_t bh[2], bl[2];
                bh[0] = *(const uint32_t*)(bp + B_HI_OFF);
                bh[1] = *(const uint32_t*)(bp + B_HI_OFF + 16);
                bl[0] = *(const uint32_t*)(bp + B_LO_OFF);
                bl[1] = *(const uint32_t*)(bp + B_LO_OFF + 16);
#pragma unroll
                for (int mi = 0; mi < 2; mi++) {
                    mma16816(acc[mi][ni], ah[mi], bh);
                    mma16816(acc[mi][ni], ah[mi], bl);
                    mma16816(acc[mi][ni], al[mi], bh);
                }
            }
        }
    }

    // ------------------------------ fused LSTM epilogue
    // Lane pair (tig even/odd) exchange: even lane gets all 4 gates of its hc.
#pragma unroll
    for (int mi = 0; mi < 2; mi++) {
        int r0 = wm * 32 + mi * 16 + g;      // local row (g-row); +8 = second row
#pragma unroll
        for (int ni = 0; ni < 8; ni++) {
            float o0 = acc[mi][ni][0], o1 = acc[mi][ni][1];
            float o2 = acc[mi][ni][2], o3 = acc[mi][ni][3];
            float p0 = __shfl_xor_sync(0xFFFFFFFFu, o0, 1);
            float p1 = __shfl_xor_sync(0xFFFFFFFFu, o1, 1);
            float p2 = __shfl_xor_sync(0xFFFFFFFFu, o2, 1);
            float p3 = __shfl_xor_sync(0xFFFFFFFFu, o3, 1);
            if ((tig & 1) == 0) {
                int col = wn * 64 + ni * 8 + 2 * tig;   // gate-i column (mult of 4)
                int np = n0 + col;
                float4 bs = *(const float4*)&g_bsum[np];
                float4 wa = *(const float4*)&g_wih0[np];
                float4 wb = *(const float4*)&g_wih1[np];
                int hc = np >> 2;
#pragma unroll
                for (int rr = 0; rr < 2; rr++) {
                    int rl = r0 + rr * 8;
                    int m = m0 + rl;
                    float x0 = x_s[rl * 2 + 0], x1 = x_s[rl * 2 + 1];
                    float vi = rr ? o2 : o0, vf = rr ? o3 : o1;
                    float vg = rr ? p2 : p0, vo = rr ? p3 : p1;
                    float pi = vi + bs.x + x0 * wa.x + x1 * wb.x;
                    float pf = vf + bs.y + x0 * wa.y + x1 * wb.y;
                    float pg = vg + bs.z + x0 * wa.z + x1 * wb.z;
                    float po = vo + bs.w + x0 * wa.w + x1 * wb.w;
                    float cp = (t == 0) ? 0.0f : g_c[m * HH + hc];
                    float cn = fsigm(pf) * cp + fsigm(pi) * ftanh(pg);
                    g_c[m * HH + hc] = cn;
                    float h = fsigm(po) * ftanh(cn);
                    __nv_bfloat16 hi = __float2bfloat16_rn(h);
                    g_h_hi[dst][m * HH + hc] = hi;
                    g_h_lo[dst][m * HH + hc] = __float2bfloat16_rn(h - __bfloat162float(hi));
                }
            }
        }
    }
}

// ------------------------------------------------------------------ head
__global__ void head_kernel(const float* __restrict__ W_out, const float* __restrict__ b_out,
                            const float* __restrict__ W_stop, const float* __restrict__ b_stop,
                            float* __restrict__ out, int t) {
    int wid = threadIdx.x >> 5, lane = threadIdx.x & 31;
    int b = blockIdx.x * 8 + wid;
    const __nv_bfloat16* hh = g_h_hi[(t & 1) ^ 1] + b * HH;
    const __nv_bfloat16* hl = g_h_lo[(t & 1) ^ 1] + b * HH;

    float s0 = 0.0f, s1 = 0.0f, ss = 0.0f;
    for (int i = lane; i < HH; i += 32) {
        float hv = __bfloat162float(hh[i]) + __bfloat162float(hl[i]);
        s0 += hv * W_out[i];
        s1 += hv * W_out[HH + i];
        ss += hv * W_stop[i];
    }
#pragma unroll
    for (int o = 16; o > 0; o >>= 1) {
        s0 += __shfl_down_sync(0xFFFFFFFFu, s0, o);
        s1 += __shfl_down_sync(0xFFFFFFFFu, s1, o);
        ss += __shfl_down_sync(0xFFFFFFFFu, ss, o);
    }
    if (lane == 0) {
        out[(b * TT + t) * 2 + 0] = s0 + b_out[0];
        out[(b * TT + t) * 2 + 1] = s1 + b_out[1];
        out[BB * TT * 2 + b * TT + t] = fsigm(ss + b_stop[0]);
    }
}

// ------------------------------------------------------------------ launch
extern "C" void kernel_launch(void* const* d_in, const int* in_sizes, int n_in,
                              void* d_out, int out_size) {
    const float* emb     = (const float*)d_in[0];
    const float* W_embed = (const float*)d_in[2];
    const float* b_embed = (const float*)d_in[3];
    const float* W_ih    = (const float*)d_in[4];
    const float* b_ih    = (const float*)d_in[5];
    const float* W_hh    = (const float*)d_in[6];
    const float* b_hh    = (const float*)d_in[7];
    const float* W_out   = (const float*)d_in[8];
    const float* b_out   = (const float*)d_in[9];
    const float* W_stop  = (const float*)d_in[10];
    const float* b_stop  = (const float*)d_in[11];
    float* out = (float*)d_out;

    cudaFuncSetAttribute(lstm_step_mma, cudaFuncAttributeMaxDynamicSharedMemorySize, SMEM_TOTAL);

    prep_w_kernel<<<NG, 256>>>(W_hh);
    prep_misc_kernel<<<NG / 256, 256>>>(b_ih, b_hh, W_ih);
    h0_kernel<<<dim3(HH / 64, BB / 64), 256>>>(emb, W_embed, b_embed);

    for (int t = 0; t < TT; t++) {
        lstm_step_mma<<<dim3(32, 4), 512, SMEM_TOTAL>>>(out, t);
        head_kernel<<<64, 256>>>(W_out, b_out, W_stop, b_stop, out, t);
    }
}

// round 4
// speedup vs baseline: 2.6348x; 1.0736x over previous
#include <cuda_runtime.h>
#include <cuda_bf16.h>
#include <math.h>
#include <cstdint>

#define BB 512
#define HH 2048
#define EE 2048
#define TT 256
#define NG 8192    // 4*H, permuted: n' = hc*4 + gate (i,f,g,o)

// ------------------------------------------------------------------ state
__device__ __align__(128) __nv_bfloat16 g_h_hi[2][BB * HH];
__device__ __align__(128) __nv_bfloat16 g_h_lo[2][BB * HH];
__device__ __align__(128) float         g_c[BB * HH];
__device__ __align__(128) __nv_bfloat16 g_w_hi[NG * HH];
__device__ __align__(128) __nv_bfloat16 g_w_lo[NG * HH];
__device__ __align__(128) float         g_bsum[NG];
__device__ __align__(128) float         g_wih0[NG];
__device__ __align__(128) float         g_wih1[NG];

// ------------------------------------------------------------------ helpers
#define CP16(dst, src)  asm volatile("cp.async.cg.shared.global [%0], [%1], 16;" :: "r"(dst), "l"(src))
#define CP_COMMIT()     asm volatile("cp.async.commit_group;" ::: "memory")
#define CP_WAIT1()      asm volatile("cp.async.wait_group 1;" ::: "memory")

#define LDSM4(r, a) \
    asm volatile("ldmatrix.sync.aligned.m8n8.x4.shared.b16 {%0,%1,%2,%3}, [%4];" \
        : "=r"((r)[0]), "=r"((r)[1]), "=r"((r)[2]), "=r"((r)[3]) : "r"(a))

__device__ __forceinline__ uint32_t smem_u32(const void* p) {
    uint32_t a;
    asm("{ .reg .u64 t; cvta.to.shared.u64 t, %1; cvt.u32.u64 %0, t; }" : "=r"(a) : "l"(p));
    return a;
}

__device__ __forceinline__ void mma16816(float* d, const uint32_t* a, const uint32_t* b) {
    asm volatile(
        "mma.sync.aligned.m16n8k16.row.col.f32.bf16.bf16.f32 "
        "{%0,%1,%2,%3}, {%4,%5,%6,%7}, {%8,%9}, {%0,%1,%2,%3};"
        : "+f"(d[0]), "+f"(d[1]), "+f"(d[2]), "+f"(d[3])
        : "r"(a[0]), "r"(a[1]), "r"(a[2]), "r"(a[3]), "r"(b[0]), "r"(b[1]));
}

__device__ __forceinline__ float fsigm(float x) { return 1.0f / (1.0f + __expf(-x)); }
__device__ __forceinline__ float ftanh(float x) {
    if (x > 8.0f) return 1.0f;
    if (x < -8.0f) return -1.0f;
    float e = __expf(2.0f * x);
    return (e - 1.0f) / (e + 1.0f);
}

// ------------------------------------------------------------------ prep
__global__ void prep_w_kernel(const float* __restrict__ W_hh) {
    int np = blockIdx.x;                 // 0..NG-1
    int g = np & 3, hc = np >> 2;
    const float* src = W_hh + (size_t)(g * HH + hc) * HH;
    __nv_bfloat16* dh = g_w_hi + (size_t)np * HH;
    __nv_bfloat16* dl = g_w_lo + (size_t)np * HH;
#pragma unroll
    for (int j = 0; j < HH / 256; j++) {
        int k = threadIdx.x + j * 256;
        float w = src[k];
        __nv_bfloat16 hi = __float2bfloat16_rn(w);
        dh[k] = hi;
        dl[k] = __float2bfloat16_rn(w - __bfloat162float(hi));
    }
}

__global__ void prep_misc_kernel(const float* __restrict__ b_ih, const float* __restrict__ b_hh,
                                 const float* __restrict__ W_ih) {
    int np = blockIdx.x * 256 + threadIdx.x;
    int g = np & 3, hc = np >> 2;
    int j = g * HH + hc;
    g_bsum[np] = b_ih[j] + b_hh[j];
    g_wih0[np] = W_ih[2 * j + 0];
    g_wih1[np] = W_ih[2 * j + 1];
}

// ------------------------------------------------------------------ h0 (fp32 SIMT, one-time)
#define KC 16
__global__ __launch_bounds__(256, 2)
void h0_kernel(const float* __restrict__ emb, const float* __restrict__ W,
               const float* __restrict__ bias) {
    __shared__ float As[KC][64];
    __shared__ float Bs[KC][64];
    int tid = threadIdx.x;
    int m0 = blockIdx.y * 64, n0 = blockIdx.x * 64;
    int lrow = tid >> 2, lk4 = (tid & 3) * 4;
    int tx_m = tid >> 4, tx_n = tid & 15;

    float acc[4][4];
#pragma unroll
    for (int i = 0; i < 4; i++)
#pragma unroll
        for (int j = 0; j < 4; j++) acc[i][j] = 0.0f;

    for (int k0 = 0; k0 < EE; k0 += KC) {
        float4 av = *(const float4*)&emb[(m0 + lrow) * EE + k0 + lk4];
        float4 bv = *(const float4*)&W[(n0 + lrow) * EE + k0 + lk4];
        __syncthreads();
        As[lk4 + 0][lrow] = av.x; As[lk4 + 1][lrow] = av.y;
        As[lk4 + 2][lrow] = av.z; As[lk4 + 3][lrow] = av.w;
        Bs[lk4 + 0][lrow] = bv.x; Bs[lk4 + 1][lrow] = bv.y;
        Bs[lk4 + 2][lrow] = bv.z; Bs[lk4 + 3][lrow] = bv.w;
        __syncthreads();
#pragma unroll
        for (int kk = 0; kk < KC; kk++) {
            float a[4], b[4];
            *(float4*)a = *(float4*)&As[kk][tx_m * 4];
            *(float4*)b = *(float4*)&Bs[kk][tx_n * 4];
#pragma unroll
            for (int mi = 0; mi < 4; mi++)
#pragma unroll
                for (int ni = 0; ni < 4; ni++) acc[mi][ni] += a[mi] * b[ni];
        }
    }
#pragma unroll
    for (int mi = 0; mi < 4; mi++) {
        int m = m0 + tx_m * 4 + mi;
#pragma unroll
        for (int ni = 0; ni < 4; ni++) {
            int n = n0 + tx_n * 4 + ni;
            float h = acc[mi][ni] + bias[n];
            __nv_bfloat16 hi = __float2bfloat16_rn(h);
            g_h_hi[0][m * HH + n] = hi;
            g_h_lo[0][m * HH + n] = __float2bfloat16_rn(h - __bfloat162float(hi));
        }
    }
}

// ------------------------------------------------------------------ main LSTM step (mma.sync bf16 3-pass, ldmatrix)
// CTA tile: 128 M x 256 N. Grid (32, 4). 512 threads = 16 warps of 32x64.
#define BKC 32           // K per chunk
#define ROWB 80          // padded row bytes (32 bf16 = 64B data + 16B pad)
#define NCHUNK 64        // 2048 / 32
#define A_HI_OFF 0
#define A_LO_OFF 10240   // 128*80
#define B_HI_OFF 20480
#define B_LO_OFF 40960   // + 256*80
#define STAGE_BYTES 61440
#define XS_OFF 0
#define STAGE0 1024
#define SMEM_TOTAL (STAGE0 + 3 * STAGE_BYTES)

__device__ __forceinline__ void load_chunk(char* smem, int stage_idx, int k0, int m0, int n0,
                                           const __nv_bfloat16* hh, const __nv_bfloat16* hl,
                                           int tid) {
    uint32_t st = smem_u32(smem + STAGE0 + stage_idx * STAGE_BYTES);
    {   // A: 128 rows x 4 chunks of 16B, one per thread
        int row = tid >> 2, c16 = tid & 3;
        uint32_t d = st + row * ROWB + c16 * 16;
        size_t goff = (size_t)(m0 + row) * HH + k0 + c16 * 8;
        CP16(d + A_HI_OFF, hh + goff);
        CP16(d + A_LO_OFF, hl + goff);
    }
#pragma unroll
    for (int p = 0; p < 2; p++) {   // B: 256 rows x 4 chunks, two per thread
        int u = tid + p * 512;
        int row = u >> 2, c16 = u & 3;
        uint32_t d = st + row * ROWB + c16 * 16;
        size_t goff = (size_t)(n0 + row) * HH + k0 + c16 * 8;
        CP16(d + B_HI_OFF, g_w_hi + goff);
        CP16(d + B_LO_OFF, g_w_lo + goff);
    }
}

__global__ __launch_bounds__(512, 1)
void lstm_step_mma(const float* __restrict__ out, int t) {
    extern __shared__ char smem[];
    float* x_s = (float*)(smem + XS_OFF);       // [128][2]
    int tid = threadIdx.x;
    int wid = tid >> 5, lane = tid & 31;
    int g = lane >> 2, tig = lane & 3;
    int wm = wid & 3, wn = wid >> 2;            // 4 x 4 warps
    int n0 = blockIdx.x * 256, m0 = blockIdx.y * 128;
    int src = t & 1, dst = src ^ 1;
    const __nv_bfloat16* hh = g_h_hi[src];
    const __nv_bfloat16* hl = g_h_lo[src];
    uint32_t sbase = smem_u32(smem + STAGE0);

    // ldmatrix per-lane row offsets (within stage)
    // A x4: lanes 0-15 -> rows (l&15), first 16B half; lanes 16-31 -> same rows, +16B
    uint32_t aoff[2];
#pragma unroll
    for (int mi = 0; mi < 2; mi++)
        aoff[mi] = (uint32_t)((wm * 32 + mi * 16 + (lane & 15)) * ROWB + ((lane >> 4) * 16));
    // B x4 (2 ni): lanes 0-7: ni0 rows +0; 8-15: ni0 rows +16; 16-23: ni1 rows +0; 24-31: ni1 rows +16
    uint32_t boff[4];
#pragma unroll
    for (int nip = 0; nip < 4; nip++)
        boff[nip] = (uint32_t)((wn * 64 + nip * 16 + ((lane >> 4) << 3) + (lane & 7)) * ROWB
                               + (((lane >> 3) & 1) * 16));

    // prev coords -> smem
    if (tid < 128) {
        float x0 = 0.0f, x1 = 0.0f;
        if (t > 0) {
            x0 = out[((m0 + tid) * TT + t - 1) * 2 + 0];
            x1 = out[((m0 + tid) * TT + t - 1) * 2 + 1];
        }
        x_s[tid * 2 + 0] = x0;
        x_s[tid * 2 + 1] = x1;
    }

    float acc[2][8][4];
#pragma unroll
    for (int mi = 0; mi < 2; mi++)
#pragma unroll
        for (int ni = 0; ni < 8; ni++)
#pragma unroll
            for (int j = 0; j < 4; j++) acc[mi][ni][j] = 0.0f;

    load_chunk(smem, 0, 0, m0, n0, hh, hl, tid);
    CP_COMMIT();
    load_chunk(smem, 1, BKC, m0, n0, hh, hl, tid);
    CP_COMMIT();

    for (int c = 0; c < NCHUNK; c++) {
        CP_WAIT1();
        __syncthreads();
        if (c + 2 < NCHUNK)
            load_chunk(smem, (c + 2) % 3, (c + 2) * BKC, m0, n0, hh, hl, tid);
        CP_COMMIT();

        uint32_t stage = sbase + (c % 3) * STAGE_BYTES;
#pragma unroll
        for (int kk = 0; kk < 2; kk++) {
            uint32_t kb = kk * 32;   // 16 k-elems * 2B
            uint32_t ah[2][4], al[2][4];
#pragma unroll
            for (int mi = 0; mi < 2; mi++) {
                LDSM4(ah[mi], stage + A_HI_OFF + aoff[mi] + kb);
                LDSM4(al[mi], stage + A_LO_OFF + aoff[mi] + kb);
            }
#pragma unroll
            for (int nip = 0; nip < 4; nip++) {
                uint32_t bh[4], bl[4];
                LDSM4(bh, stage + B_HI_OFF + boff[nip] + kb);
                LDSM4(bl, stage + B_LO_OFF + boff[nip] + kb);
                // bh = {ni0.b0, ni0.b1, ni1.b0, ni1.b1}
#pragma unroll
                for (int ni2 = 0; ni2 < 2; ni2++)
#pragma unroll
                    for (int mi = 0; mi < 2; mi++)
                        mma16816(acc[mi][nip * 2 + ni2], ah[mi], bh + ni2 * 2);
#pragma unroll
                for (int ni2 = 0; ni2 < 2; ni2++)
#pragma unroll
                    for (int mi = 0; mi < 2; mi++)
                        mma16816(acc[mi][nip * 2 + ni2], ah[mi], bl + ni2 * 2);
#pragma unroll
                for (int ni2 = 0; ni2 < 2; ni2++)
#pragma unroll
                    for (int mi = 0; mi < 2; mi++)
                        mma16816(acc[mi][nip * 2 + ni2], al[mi], bh + ni2 * 2);
            }
        }
    }

    // ------------------------------ fused LSTM epilogue
    // Lane pair (tig even/odd) exchange: even lane gets all 4 gates of its hc.
#pragma unroll
    for (int mi = 0; mi < 2; mi++) {
        int r0 = wm * 32 + mi * 16 + g;      // local row (g-row); +8 = second row
#pragma unroll
        for (int ni = 0; ni < 8; ni++) {
            float o0 = acc[mi][ni][0], o1 = acc[mi][ni][1];
            float o2 = acc[mi][ni][2], o3 = acc[mi][ni][3];
            float p0 = __shfl_xor_sync(0xFFFFFFFFu, o0, 1);
            float p1 = __shfl_xor_sync(0xFFFFFFFFu, o1, 1);
            float p2 = __shfl_xor_sync(0xFFFFFFFFu, o2, 1);
            float p3 = __shfl_xor_sync(0xFFFFFFFFu, o3, 1);
            if ((tig & 1) == 0) {
                int col = wn * 64 + ni * 8 + 2 * tig;   // gate-i column (mult of 4)
                int np = n0 + col;
                float4 bs = *(const float4*)&g_bsum[np];
                float4 wa = *(const float4*)&g_wih0[np];
                float4 wb = *(const float4*)&g_wih1[np];
                int hc = np >> 2;
#pragma unroll
                for (int rr = 0; rr < 2; rr++) {
                    int rl = r0 + rr * 8;
                    int m = m0 + rl;
                    float x0 = x_s[rl * 2 + 0], x1 = x_s[rl * 2 + 1];
                    float vi = rr ? o2 : o0, vf = rr ? o3 : o1;
                    float vg = rr ? p2 : p0, vo = rr ? p3 : p1;
                    float pi = vi + bs.x + x0 * wa.x + x1 * wb.x;
                    float pf = vf + bs.y + x0 * wa.y + x1 * wb.y;
                    float pg = vg + bs.z + x0 * wa.z + x1 * wb.z;
                    float po = vo + bs.w + x0 * wa.w + x1 * wb.w;
                    float cp = (t == 0) ? 0.0f : g_c[m * HH + hc];
                    float cn = fsigm(pf) * cp + fsigm(pi) * ftanh(pg);
                    g_c[m * HH + hc] = cn;
                    float h = fsigm(po) * ftanh(cn);
                    __nv_bfloat16 hi = __float2bfloat16_rn(h);
                    g_h_hi[dst][m * HH + hc] = hi;
                    g_h_lo[dst][m * HH + hc] = __float2bfloat16_rn(h - __bfloat162float(hi));
                }
            }
        }
    }
}

// ------------------------------------------------------------------ head (vectorized)
__global__ void head_kernel(const float* __restrict__ W_out, const float* __restrict__ b_out,
                            const float* __restrict__ W_stop, const float* __restrict__ b_stop,
                            float* __restrict__ out, int t) {
    int wid = threadIdx.x >> 5, lane = threadIdx.x & 31;
    int b = blockIdx.x * 8 + wid;
    const uint4* hh4 = (const uint4*)(g_h_hi[(t & 1) ^ 1] + b * HH);
    const uint4* hl4 = (const uint4*)(g_h_lo[(t & 1) ^ 1] + b * HH);

    float s0 = 0.0f, s1 = 0.0f, ss = 0.0f;
#pragma unroll
    for (int it = 0; it < 8; it++) {
        int v = it * 32 + lane;           // uint4 index: 8 bf16 each
        uint4 vh = hh4[v], vl = hl4[v];
        int e = v * 8;
#pragma unroll
        for (int w = 0; w < 4; w++) {
            uint32_t uh = (&vh.x)[w], ul = (&vl.x)[w];
            float2 fh = __bfloat1622float2(*(__nv_bfloat162*)&uh);
            float2 fl = __bfloat1622float2(*(__nv_bfloat162*)&ul);
            float h0 = fh.x + fl.x, h1 = fh.y + fl.y;
            int i = e + w * 2;
            float2 w0 = *(const float2*)&W_out[i];
            float2 w1 = *(const float2*)&W_out[HH + i];
            float2 wsv = *(const float2*)&W_stop[i];
            s0 += h0 * w0.x + h1 * w0.y;
            s1 += h0 * w1.x + h1 * w1.y;
            ss += h0 * wsv.x + h1 * wsv.y;
        }
    }
#pragma unroll
    for (int o = 16; o > 0; o >>= 1) {
        s0 += __shfl_down_sync(0xFFFFFFFFu, s0, o);
        s1 += __shfl_down_sync(0xFFFFFFFFu, s1, o);
        ss += __shfl_down_sync(0xFFFFFFFFu, ss, o);
    }
    if (lane == 0) {
        out[(b * TT + t) * 2 + 0] = s0 + b_out[0];
        out[(b * TT + t) * 2 + 1] = s1 + b_out[1];
        out[BB * TT * 2 + b * TT + t] = fsigm(ss + b_stop[0]);
    }
}

// ------------------------------------------------------------------ launch
extern "C" void kernel_launch(void* const* d_in, const int* in_sizes, int n_in,
                              void* d_out, int out_size) {
    const float* emb     = (const float*)d_in[0];
    const float* W_embed = (const float*)d_in[2];
    const float* b_embed = (const float*)d_in[3];
    const float* W_ih    = (const float*)d_in[4];
    const float* b_ih    = (const float*)d_in[5];
    const float* W_hh    = (const float*)d_in[6];
    const float* b_hh    = (const float*)d_in[7];
    const float* W_out   = (const float*)d_in[8];
    const float* b_out   = (const float*)d_in[9];
    const float* W_stop  = (const float*)d_in[10];
    const float* b_stop  = (const float*)d_in[11];
    float* out = (float*)d_out;

    cudaFuncSetAttribute(lstm_step_mma, cudaFuncAttributeMaxDynamicSharedMemorySize, SMEM_TOTAL);

    prep_w_kernel<<<NG, 256>>>(W_hh);
    prep_misc_kernel<<<NG / 256, 256>>>(b_ih, b_hh, W_ih);
    h0_kernel<<<dim3(HH / 64, BB / 64), 256>>>(emb, W_embed, b_embed);

    for (int t = 0; t < TT; t++) {
        lstm_step_mma<<<dim3(32, 4), 512, SMEM_TOTAL>>>(out, t);
        head_kernel<<<64, 256>>>(W_out, b_out, W_stop, b_stop, out, t);
    }
}